// round 14
// baseline (speedup 1.0000x reference)
#include <cuda_runtime.h>
#include <cuda_fp16.h>

typedef __half fp16;

#define B_ 2
#define S_ 4096
#define D_ 512
#define M_ (B_ * S_)
#define MAXFLAG (1 << 18)

// ---------------- scratch ----------------
__device__ fp16 g_wh[4][D_ * D_];
__device__ fp16 g_wl[4][D_ * D_];
__device__ fp16 g_qh[(size_t)M_ * D_];
__device__ fp16 g_ql[(size_t)M_ * D_];
__device__ fp16 g_kh[(size_t)M_ * D_];
__device__ fp16 g_kl[(size_t)M_ * D_];
__device__ fp16 g_vf[(size_t)M_ * D_];
__device__ float g_cf[(size_t)M_ * D_];           // ctx fp32 (pre-fixup)
__device__ int g_nflag;
__device__ unsigned g_flags[MAXFLAG];
__device__ unsigned g_seen[1 << 20];              // 4MB dedupe bitmap (2*4096*4096 bits)

// ---------------- ptx helpers ----------------
__device__ __forceinline__ unsigned smaddr(const void* p) {
    return (unsigned)__cvta_generic_to_shared(p);
}
__device__ __forceinline__ void ldsm4(unsigned* r, unsigned a) {
    asm volatile("ldmatrix.sync.aligned.m8n8.x4.shared.b16 {%0,%1,%2,%3},[%4];"
                 : "=r"(r[0]), "=r"(r[1]), "=r"(r[2]), "=r"(r[3]) : "r"(a));
}
__device__ __forceinline__ void ldsm2(unsigned* r, unsigned a) {
    asm volatile("ldmatrix.sync.aligned.m8n8.x2.shared.b16 {%0,%1},[%2];"
                 : "=r"(r[0]), "=r"(r[1]) : "r"(a));
}
__device__ __forceinline__ void ldsm2t(unsigned* r, unsigned a) {
    asm volatile("ldmatrix.sync.aligned.m8n8.x2.trans.shared.b16 {%0,%1},[%2];"
                 : "=r"(r[0]), "=r"(r[1]) : "r"(a));
}
__device__ __forceinline__ void mma16816h(float* c, const unsigned* a, const unsigned* b) {
    asm volatile(
        "mma.sync.aligned.m16n8k16.row.col.f32.f16.f16.f32 "
        "{%0,%1,%2,%3},{%4,%5,%6,%7},{%8,%9},{%0,%1,%2,%3};"
        : "+f"(c[0]), "+f"(c[1]), "+f"(c[2]), "+f"(c[3])
        : "r"(a[0]), "r"(a[1]), "r"(a[2]), "r"(a[3]), "r"(b[0]), "r"(b[1]));
}
__device__ __forceinline__ void cpa16(unsigned d, const void* g) {
    asm volatile("cp.async.cg.shared.global [%0], [%1], 16;" :: "r"(d), "l"(g));
}
__device__ __forceinline__ void cpcommit() { asm volatile("cp.async.commit_group;"); }
__device__ __forceinline__ void cpwait0()  { asm volatile("cp.async.wait_group 0;" ::: "memory"); }

// ---------------- small utility kernels ----------------
__global__ __launch_bounds__(256) void zero_kernel() {
    int i = blockIdx.x * 256 + threadIdx.x;       // 0..262143
    *(uint4*)&g_seen[i * 4] = make_uint4(0, 0, 0, 0);
    if (i == 0) g_nflag = 0;
}

__global__ __launch_bounds__(256) void split_kernel(
    const float* __restrict__ in, fp16* __restrict__ hi, fp16* __restrict__ lo, int n)
{
    int i = blockIdx.x * 256 + threadIdx.x;
    if (i < n) {
        float v = in[i];
        fp16 h = __float2half_rn(v);
        hi[i] = h;
        lo[i] = __float2half_rn(v - __half2float(h));
    }
}

// ---------------- merged QKV projection (unchanged from round 12) -----------
__global__ __launch_bounds__(256) void gemm_qkv(
    const float* __restrict__ x,
    const fp16* __restrict__ wh, const fp16* __restrict__ wl,
    fp16* __restrict__ qh, fp16* __restrict__ ql,
    fp16* __restrict__ kh, fp16* __restrict__ kl,
    fp16* __restrict__ vf)
{
    extern __shared__ fp16 qkvsm[];
    fp16* sAh = qkvsm;
    fp16* sAl = qkvsm + 5120;

    const int tid = threadIdx.x, lane = tid & 31, warp = tid >> 5;
    const int m0 = blockIdx.y * 128, n0 = blockIdx.x * 64;
    const int wm = warp >> 1, wn = warp & 1;

    float acc[3][2][4][4];
#pragma unroll
    for (int w = 0; w < 3; w++)
#pragma unroll
        for (int a = 0; a < 2; a++)
#pragma unroll
            for (int b = 0; b < 4; b++)
#pragma unroll
                for (int c = 0; c < 4; c++) acc[w][a][b][c] = 0.0f;

    for (int k0 = 0; k0 < 512; k0 += 32) {
        __syncthreads();
#pragma unroll
        for (int j = 0; j < 4; j++) {
            int u = tid + j * 256;
            int row = u >> 3, c4 = u & 7;
            float4 v = *(const float4*)&x[(size_t)(m0 + row) * 512 + k0 + c4 * 4];
            fp16 h0 = __float2half_rn(v.x), h1 = __float2half_rn(v.y);
            fp16 h2 = __float2half_rn(v.z), h3 = __float2half_rn(v.w);
            fp16 l0 = __float2half_rn(v.x - __half2float(h0));
            fp16 l1 = __float2half_rn(v.y - __half2float(h1));
            fp16 l2 = __float2half_rn(v.z - __half2float(h2));
            fp16 l3 = __float2half_rn(v.w - __half2float(h3));
            int off = row * 40 + c4 * 4;
            *(__half2*)&sAh[off]     = __half2(h0, h1);
            *(__half2*)&sAh[off + 2] = __half2(h2, h3);
            *(__half2*)&sAl[off]     = __half2(l0, l1);
            *(__half2*)&sAl[off + 2] = __half2(l2, l3);
        }
#pragma unroll
        for (int j = 0; j < 6; j++) {
            int u = tid + j * 256;
            int w = u >> 9, rem = u & 511;
            int hh = rem >> 8, r2 = rem & 255;
            int row = r2 >> 2, c4 = r2 & 3;
            const fp16* src = (hh ? wl : wh) + (size_t)w * D_ * D_
                              + (size_t)(n0 + row) * 512 + k0 + c4 * 8;
            fp16* dst = qkvsm + 10240 + (w * 2 + hh) * 2560 + row * 40 + c4 * 8;
            *(uint4*)dst = *(const uint4*)src;
        }
        __syncthreads();

#pragma unroll
        for (int kc = 0; kc < 2; kc++) {
            unsigned ah[2][4], al[2][4];
#pragma unroll
            for (int mi = 0; mi < 2; mi++) {
                int r = wm * 32 + mi * 16 + (lane & 15);
                int cc = kc * 16 + (lane >> 4) * 8;
                ldsm4(ah[mi], smaddr(&sAh[r * 40 + cc]));
                ldsm4(al[mi], smaddr(&sAl[r * 40 + cc]));
            }
#pragma unroll
            for (int w = 0; w < 3; w++) {
#pragma unroll
                for (int ni = 0; ni < 4; ni++) {
                    int r = wn * 32 + ni * 8 + (lane & 7);
                    int cc = kc * 16 + ((lane >> 3) & 1) * 8;
                    const fp16* wbh = qkvsm + 10240 + (w * 2 + 0) * 2560;
                    const fp16* wbl = qkvsm + 10240 + (w * 2 + 1) * 2560;
                    unsigned bh[2], bl[2];
                    ldsm2(bh, smaddr(&wbh[r * 40 + cc]));
                    ldsm2(bl, smaddr(&wbl[r * 40 + cc]));
#pragma unroll
                    for (int mi = 0; mi < 2; mi++) {
                        mma16816h(acc[w][mi][ni], ah[mi], bh);
                        mma16816h(acc[w][mi][ni], ah[mi], bl);
                        mma16816h(acc[w][mi][ni], al[mi], bh);
                    }
                }
            }
        }
    }

#pragma unroll
    for (int w = 0; w < 3; w++)
#pragma unroll
        for (int mi = 0; mi < 2; mi++)
#pragma unroll
            for (int ni = 0; ni < 4; ni++)
#pragma unroll
                for (int half = 0; half < 2; half++) {
                    int row = m0 + wm * 32 + mi * 16 + (lane >> 2) + half * 8;
                    int col = n0 + wn * 32 + ni * 8 + (lane & 3) * 2;
                    float v0 = acc[w][mi][ni][half * 2 + 0];
                    float v1 = acc[w][mi][ni][half * 2 + 1];
                    size_t off = (size_t)row * 512 + col;
                    if (w == 2) {
                        *(__half2*)&vf[off] = __floats2half2_rn(v0, v1);
                    } else {
                        fp16 h0 = __float2half_rn(v0), h1 = __float2half_rn(v1);
                        fp16 l0 = __float2half_rn(v0 - __half2float(h0));
                        fp16 l1 = __float2half_rn(v1 - __half2float(h1));
                        fp16* Ch = (w == 0) ? qh : kh;
                        fp16* Cl = (w == 0) ? ql : kl;
                        *(__half2*)&Ch[off] = __half2(h0, h1);
                        *(__half2*)&Cl[off] = __half2(l0, l1);
                    }
                }
}

// ---------------- output projection (unchanged from round 12) ---------------
__global__ __launch_bounds__(256) void gemm_out(
    const float* __restrict__ A,
    const fp16* __restrict__ Wh, const fp16* __restrict__ Wl,
    float* __restrict__ Cf)
{
    __shared__ fp16 sAh[128 * 40], sAl[128 * 40], sWh[64 * 40], sWl[64 * 40];

    const int tid = threadIdx.x, lane = tid & 31, warp = tid >> 5;
    const int m0 = blockIdx.y * 128, n0 = blockIdx.x * 64;
    const int wm = warp >> 1, wn = warp & 1;

    float acc[2][4][4];
#pragma unroll
    for (int a = 0; a < 2; a++)
#pragma unroll
        for (int b = 0; b < 4; b++)
#pragma unroll
            for (int c = 0; c < 4; c++) acc[a][b][c] = 0.0f;

    for (int k0 = 0; k0 < 512; k0 += 32) {
        __syncthreads();
#pragma unroll
        for (int j = 0; j < 4; j++) {
            int u = tid + j * 256;
            int row = u >> 3, c4 = u & 7;
            float4 v = *(const float4*)&A[(size_t)(m0 + row) * 512 + k0 + c4 * 4];
            fp16 h0 = __float2half_rn(v.x), h1 = __float2half_rn(v.y);
            fp16 h2 = __float2half_rn(v.z), h3 = __float2half_rn(v.w);
            fp16 l0 = __float2half_rn(v.x - __half2float(h0));
            fp16 l1 = __float2half_rn(v.y - __half2float(h1));
            fp16 l2 = __float2half_rn(v.z - __half2float(h2));
            fp16 l3 = __float2half_rn(v.w - __half2float(h3));
            int off = row * 40 + c4 * 4;
            *(__half2*)&sAh[off]     = __half2(h0, h1);
            *(__half2*)&sAh[off + 2] = __half2(h2, h3);
            *(__half2*)&sAl[off]     = __half2(l0, l1);
            *(__half2*)&sAl[off + 2] = __half2(l2, l3);
        }
#pragma unroll
        for (int j = 0; j < 2; j++) {
            int u = tid + j * 256;
            int half = u >> 8, rem = u & 255;
            int row = rem >> 2, c4 = rem & 3;
            const fp16* src = (half ? Wl : Wh) + (size_t)(n0 + row) * 512 + k0 + c4 * 8;
            fp16* dst = (half ? sWl : sWh) + row * 40 + c4 * 8;
            *(uint4*)dst = *(const uint4*)src;
        }
        __syncthreads();

#pragma unroll
        for (int kc = 0; kc < 2; kc++) {
            unsigned ah[2][4], al[2][4];
#pragma unroll
            for (int mi = 0; mi < 2; mi++) {
                int r = wm * 32 + mi * 16 + (lane & 15);
                int cc = kc * 16 + (lane >> 4) * 8;
                ldsm4(ah[mi], smaddr(&sAh[r * 40 + cc]));
                ldsm4(al[mi], smaddr(&sAl[r * 40 + cc]));
            }
#pragma unroll
            for (int ni = 0; ni < 4; ni++) {
                int r = wn * 32 + ni * 8 + (lane & 7);
                int cc = kc * 16 + ((lane >> 3) & 1) * 8;
                unsigned bh[2], bl[2];
                ldsm2(bh, smaddr(&sWh[r * 40 + cc]));
                ldsm2(bl, smaddr(&sWl[r * 40 + cc]));
#pragma unroll
                for (int mi = 0; mi < 2; mi++) {
                    mma16816h(acc[mi][ni], ah[mi], bh);
                    mma16816h(acc[mi][ni], ah[mi], bl);
                    mma16816h(acc[mi][ni], al[mi], bh);
                }
            }
        }
    }

#pragma unroll
    for (int mi = 0; mi < 2; mi++)
#pragma unroll
        for (int ni = 0; ni < 4; ni++)
#pragma unroll
            for (int half = 0; half < 2; half++) {
                int row = m0 + wm * 32 + mi * 16 + (lane >> 2) + half * 8;
                int col = n0 + wn * 32 + ni * 8 + (lane & 3) * 2;
                float v0 = acc[mi][ni][half * 2 + 0];
                float v1 = acc[mi][ni][half * 2 + 1];
                *(float2*)&Cf[(size_t)row * 512 + col] =
                    make_float2(fmaxf(v0, 0.f), fmaxf(v1, 0.f));
            }
}

// ---------------- fused attention: interleaved balanced tiles ---------------
// grid (64, 2). CTA owns q rows of tile tA=pair (local rows 0-31, warps with
// qhalf=0) and tile tB=127-pair (local rows 32-63, qhalf=1). ONE KV stream of
// 128 trips. Per trip each half is full (it<=t) or masked (scores for flag
// detection + PV with constant 1/8, done before the softmax barriers).
// Full-path trips per CTA = (tA+1)+(tB+1) = 129 constant -> balanced.
#define QSTR 520
#define KVELEM 33280
#define SSCOFF 133120
#define SCH 2304            // floats per head (64 local rows * 36)
#define SATOFF 206848
#define ATH 1536            // halfs per head (64 * 24)
#define SMEMTOT 231424

__global__ __launch_bounds__(512, 1) void fused_attn(
    const fp16* __restrict__ qhp, const fp16* __restrict__ khp,
    const fp16* __restrict__ vfp)
{
    extern __shared__ char smem[];
    fp16* kv = (fp16*)smem;
    float* ssc = (float*)(smem + SSCOFF);
    fp16* sat = (fp16*)(smem + SATOFF);

    const int tid = threadIdx.x, lane = tid & 31, w = tid >> 5;
    const int h = w & 7, qhalf = w >> 3;
    const int pair = blockIdx.x, b = blockIdx.y;
    const int tA = pair, tB = 127 - pair;
    const int tmine = qhalf ? tB : tA;
    const size_t kvbase = (size_t)b * S_ * D_;
    const int browbase = b * S_;
    const unsigned AFC = 0x30003000u;            // half2(0.125, 0.125)
    const unsigned afc[4] = {AFC, AFC, AFC, AFC};

    // ---- stage Q (local rows 0-31 <- tile tA, 32-63 <- tile tB) ----
#pragma unroll
    for (int j = 0; j < 8; j++) {
        int u = tid + j * 512;
        int row = u >> 6, cc = u & 63;
        int grow = (row < 32) ? (tA * 32 + row) : (tB * 32 + row - 32);
        const fp16* src = qhp + (size_t)(browbase + grow) * 512 + cc * 8;
        *(uint4*)&kv[row * QSTR + cc * 8] = *(const uint4*)src;
    }
    __syncthreads();

    unsigned qf[2][4][4];
#pragma unroll
    for (int mi = 0; mi < 2; mi++)
#pragma unroll
        for (int dc = 0; dc < 4; dc++) {
            int row = qhalf * 32 + mi * 16 + (lane & 15);
            int col = h * 64 + dc * 16 + (lane >> 4) * 8;
            ldsm4(qf[mi][dc], smaddr(&kv[row * QSTR + col]));
        }
    __syncthreads();

    float cacc[2][8][4];
#pragma unroll
    for (int mi = 0; mi < 2; mi++)
#pragma unroll
        for (int ni = 0; ni < 8; ni++)
#pragma unroll
            for (int c = 0; c < 4; c++) cacc[mi][ni][c] = 0.0f;

#pragma unroll
    for (int j = 0; j < 8; j++) {
        int c = tid + j * 512;
        int arr = c >> 11, rem = c & 2047;
        int r = rem >> 6, cc = rem & 63;
        size_t goff = kvbase + (size_t)r * 512 + cc * 8;
        const fp16* src = (arr == 0) ? (khp + goff) : (vfp + goff);
        cpa16(smaddr(kv + arr * 16640 + r * 520 + cc * 8), src);
    }
    cpcommit();

#pragma unroll 1
    for (int it = 0; it < 128; it++) {
        fp16* buf = kv + (it & 1) * KVELEM;
        const fp16* Kf = buf;
        const fp16* Vf = buf + 16640;
        const int kbase = it * 32;

        cpwait0();
        __syncthreads();

        if (it + 1 < 128) {
            fp16* nb = kv + ((it + 1) & 1) * KVELEM;
            const size_t rowoff = kvbase + (size_t)(it + 1) * 32 * 512;
#pragma unroll
            for (int j = 0; j < 8; j++) {
                int c = tid + j * 512;
                int arr = c >> 11, rem = c & 2047;
                int r = rem >> 6, cc = rem & 63;
                size_t goff = rowoff + (size_t)r * 512 + cc * 8;
                const fp16* src = (arr == 0) ? (khp + goff) : (vfp + goff);
                cpa16(smaddr(nb + arr * 16640 + r * 520 + cc * 8), src);
            }
            cpcommit();
        }

        const bool full = (it <= tmine);

        if (full) {
            // ---- scores -> ssc (this half's 32 local rows) ----
#pragma unroll
            for (int kc = 0; kc < 2; kc++) {
                float cs[2][2][4];
#pragma unroll
                for (int mi = 0; mi < 2; mi++)
#pragma unroll
                    for (int ni = 0; ni < 2; ni++)
#pragma unroll
                        for (int c = 0; c < 4; c++) cs[mi][ni][c] = 0.0f;
#pragma unroll
                for (int dc = 0; dc < 4; dc++) {
                    unsigned k2[2][2];
#pragma unroll
                    for (int ni = 0; ni < 2; ni++) {
                        int kr = kc * 16 + ni * 8 + (lane & 7);
                        int col = h * 64 + dc * 16 + ((lane >> 3) & 1) * 8;
                        ldsm2(k2[ni], smaddr(&Kf[kr * 520 + col]));
                    }
#pragma unroll
                    for (int mi = 0; mi < 2; mi++)
#pragma unroll
                        for (int ni = 0; ni < 2; ni++)
                            mma16816h(cs[mi][ni], qf[mi][dc], k2[ni]);
                }
#pragma unroll
                for (int mi = 0; mi < 2; mi++)
#pragma unroll
                    for (int ni = 0; ni < 2; ni++) {
                        int row = qhalf * 32 + mi * 16 + (lane >> 2);
                        int col = kc * 16 + ni * 8 + (lane & 3) * 2;
                        *(float2*)&ssc[h * SCH + row * 36 + col] =
                            make_float2(cs[mi][ni][0], cs[mi][ni][1]);
                        *(float2*)&ssc[h * SCH + (row + 8) * 36 + col] =
                            make_float2(cs[mi][ni][2], cs[mi][ni][3]);
                    }
            }
        } else {
            // ---- masked: scores for flag detection + PV with attn=1/8 ----
#pragma unroll
            for (int kc = 0; kc < 2; kc++) {
                float cs[2][2][4];
#pragma unroll
                for (int mi = 0; mi < 2; mi++)
#pragma unroll
                    for (int ni = 0; ni < 2; ni++)
#pragma unroll
                        for (int c = 0; c < 4; c++) cs[mi][ni][c] = 0.0f;
#pragma unroll
                for (int dc = 0; dc < 4; dc++) {
                    unsigned k2[2][2];
#pragma unroll
                    for (int ni = 0; ni < 2; ni++) {
                        int kr = kc * 16 + ni * 8 + (lane & 7);
                        int col = h * 64 + dc * 16 + ((lane >> 3) & 1) * 8;
                        ldsm2(k2[ni], smaddr(&Kf[kr * 520 + col]));
                    }
#pragma unroll
                    for (int mi = 0; mi < 2; mi++)
#pragma unroll
                        for (int ni = 0; ni < 2; ni++)
                            mma16816h(cs[mi][ni], qf[mi][dc], k2[ni]);
                }
                float mx = 0.0f;
#pragma unroll
                for (int mi = 0; mi < 2; mi++)
#pragma unroll
                    for (int ni = 0; ni < 2; ni++)
#pragma unroll
                        for (int c = 0; c < 4; c++)
                            mx = fmaxf(mx, fabsf(cs[mi][ni][c]));
                if (mx >= 31.5f) {      // rare; fixup dedupes multi-head flags
#pragma unroll
                    for (int mi = 0; mi < 2; mi++)
#pragma unroll
                        for (int ni = 0; ni < 2; ni++)
#pragma unroll
                            for (int c = 0; c < 4; c++)
                                if (fabsf(cs[mi][ni][c]) >= 31.5f) {
                                    int qg = tmine * 32 + mi * 16 + (lane >> 2)
                                             + ((c >> 1) ? 8 : 0);
                                    int kg = kbase + kc * 16 + ni * 8
                                             + (lane & 3) * 2 + (c & 1);
                                    int idx = atomicAdd(&g_nflag, 1);
                                    if (idx < MAXFLAG)
                                        g_flags[idx] = ((unsigned)b << 24)
                                            | ((unsigned)qg << 12) | (unsigned)kg;
                                }
                }
                // PV with constant attn = 1/8 (bit-identical to sat=0.125 path)
#pragma unroll
                for (int ni = 0; ni < 8; ni++) {
                    unsigned v2[2];
                    ldsm2t(v2, smaddr(&Vf[(kc * 16 + (lane & 15)) * 520 + h * 64 + ni * 8]));
#pragma unroll
                    for (int mi = 0; mi < 2; mi++)
                        mma16816h(cacc[mi][ni], afc, v2);
                }
            }
        }
        __syncthreads();

        // ---- softmax + PV sub-phases (only halves that are full this trip) ---
#pragma unroll
        for (int sub = 0; sub < 2; sub++) {
            {
                int q = tid >> 3;                       // local row 0..63
                int kl = (tid & 7) * 2;
                int tq = (q < 32) ? tA : tB;
                if (it <= tq) {
                    int qg = (q < 32) ? (tA * 32 + q) : (tB * 32 + q - 32);
                    int kg = kbase + sub * 16 + kl;

                    float2 s2[8];
#pragma unroll
                    for (int hh = 0; hh < 8; hh++)
                        s2[hh] = *(float2*)&ssc[hh * SCH + q * 36 + sub * 16 + kl];

                    float p0[8], p1[8];
                    if (kg > qg) {
                        float mx = fabsf(s2[0].x);
#pragma unroll
                        for (int hh = 1; hh < 8; hh++) mx = fmaxf(mx, fabsf(s2[hh].x));
                        if (mx >= 31.5f) {
                            int idx = atomicAdd(&g_nflag, 1);
                            if (idx < MAXFLAG)
                                g_flags[idx] = ((unsigned)b << 24) | ((unsigned)qg << 12) | (unsigned)kg;
                        }
#pragma unroll
                        for (int hh = 0; hh < 8; hh++) p0[hh] = 0.125f;
                    } else {
                        float sum = 0.0f;
#pragma unroll
                        for (int hh = 0; hh < 8; hh++) {
                            p0[hh] = __expf(s2[hh].x * 0.125f);
                            sum += p0[hh];
                        }
                        float inv = 1.0f / sum;
#pragma unroll
                        for (int hh = 0; hh < 8; hh++) p0[hh] *= inv;
                    }
                    if (kg + 1 > qg) {
                        float mx = fabsf(s2[0].y);
#pragma unroll
                        for (int hh = 1; hh < 8; hh++) mx = fmaxf(mx, fabsf(s2[hh].y));
                        if (mx >= 31.5f) {
                            int idx = atomicAdd(&g_nflag, 1);
                            if (idx < MAXFLAG)
                                g_flags[idx] = ((unsigned)b << 24) | ((unsigned)qg << 12) | (unsigned)(kg + 1);
                        }
#pragma unroll
                        for (int hh = 0; hh < 8; hh++) p1[hh] = 0.125f;
                    } else {
                        float sum = 0.0f;
#pragma unroll
                        for (int hh = 0; hh < 8; hh++) {
                            p1[hh] = __expf(s2[hh].y * 0.125f);
                            sum += p1[hh];
                        }
                        float inv = 1.0f / sum;
#pragma unroll
                        for (int hh = 0; hh < 8; hh++) p1[hh] *= inv;
                    }
#pragma unroll
                    for (int hh = 0; hh < 8; hh++)
                        *(__half2*)&sat[hh * ATH + q * 24 + kl] =
                            __floats2half2_rn(p0[hh], p1[hh]);
                }
            }
            __syncthreads();

            if (full) {
                unsigned af[2][4];
#pragma unroll
                for (int mi = 0; mi < 2; mi++) {
                    int row = qhalf * 32 + mi * 16 + (lane & 15);
                    ldsm4(af[mi], smaddr(&sat[h * ATH + row * 24 + (lane >> 4) * 8]));
                }
#pragma unroll
                for (int ni = 0; ni < 8; ni++) {
                    unsigned v2[2];
                    ldsm2t(v2, smaddr(&Vf[(sub * 16 + (lane & 15)) * 520 + h * 64 + ni * 8]));
#pragma unroll
                    for (int mi = 0; mi < 2; mi++)
                        mma16816h(cacc[mi][ni], af[mi], v2);
                }
            }
            if (sub == 0) __syncthreads();
        }
    }

    // ---- epilogue: ctx -> fp32 scratch (global rows of this warp's tile) ----
#pragma unroll
    for (int mi = 0; mi < 2; mi++)
#pragma unroll
        for (int ni = 0; ni < 8; ni++)
#pragma unroll
            for (int hf = 0; hf < 2; hf++) {
                int row = browbase + tmine * 32 + mi * 16 + (lane >> 2) + hf * 8;
                int col = h * 64 + ni * 8 + (lane & 3) * 2;
                size_t off = (size_t)row * 512 + col;
                *(float2*)&g_cf[off] =
                    make_float2(cacc[mi][ni][hf * 2 + 0], cacc[mi][ni][hf * 2 + 1]);
            }
}

// ---------------- fixup: exact correction, deduped via bitmap ---------------
__global__ __launch_bounds__(32) void fixup_kernel(
    const fp16* __restrict__ qh, const fp16* __restrict__ ql,
    const fp16* __restrict__ kh, const fp16* __restrict__ kl,
    const fp16* __restrict__ vf)
{
    const int lane = threadIdx.x;
    int count = g_nflag;
    if (count > MAXFLAG) count = MAXFLAG;

    for (int i = blockIdx.x; i < count; i += gridDim.x) {
        unsigned f = g_flags[i];
        int b = f >> 24;
        int qg = (f >> 12) & 4095;
        int kg = f & 4095;

        // dedupe: only the first claimant applies the correction
        unsigned claimed;
        if (lane == 0) {
            unsigned pidx = (((unsigned)b * 4096u) + (unsigned)qg) * 4096u + (unsigned)kg;
            unsigned old = atomicOr(&g_seen[pidx >> 5], 1u << (pidx & 31));
            claimed = !(old & (1u << (pidx & 31)));
        }
        claimed = __shfl_sync(0xFFFFFFFFu, claimed, 0);
        if (!claimed) continue;

        size_t qrow = (size_t)(b * S_ + qg) * 512;
        size_t krow = (size_t)(b * S_ + kg) * 512;

        float t[8];
#pragma unroll
        for (int hh = 0; hh < 8; hh++) {
            float se = 0.0f;
#pragma unroll
            for (int r = 0; r < 2; r++) {
                int d = hh * 64 + r * 32 + lane;
                float qv = __half2float(qh[qrow + d]) + __half2float(ql[qrow + d]);
                float kv = __half2float(kh[krow + d]) + __half2float(kl[krow + d]);
                se = fmaf(qv, kv, se);
            }
#pragma unroll
            for (int o = 16; o; o >>= 1)
                se += __shfl_xor_sync(0xFFFFFFFFu, se, o);
            t[hh] = 8.0f * rintf(se * 0.015625f);
        }
        float e[8], sum = 0.0f;
#pragma unroll
        for (int hh = 0; hh < 8; hh++) { e[hh] = __expf(t[hh]); sum += e[hh]; }
        float inv = 1.0f / sum;

#pragma unroll
        for (int j = 0; j < 16; j++) {
            int c = j * 32 + lane;
            int hh = c >> 6;
            float corr = (e[hh] * inv - 0.125f) * __half2float(vf[krow + c]);
            atomicAdd(&g_cf[qrow + c], corr);
        }
    }
}

// ---------------------------------------------------------------------------
extern "C" void kernel_launch(void* const* d_in, const int* in_sizes, int n_in,
                              void* d_out, int out_size)
{
    const float* x  = (const float*)d_in[0];
    const float* W[4] = {(const float*)d_in[1], (const float*)d_in[2],
                         (const float*)d_in[3], (const float*)d_in[4]};
    float* out = (float*)d_out;

    fp16 *wh, *wl, *qh, *ql, *kh, *kl, *vf;
    float* cf;
    cudaGetSymbolAddress((void**)&wh, g_wh);
    cudaGetSymbolAddress((void**)&wl, g_wl);
    cudaGetSymbolAddress((void**)&qh, g_qh);
    cudaGetSymbolAddress((void**)&ql, g_ql);
    cudaGetSymbolAddress((void**)&kh, g_kh);
    cudaGetSymbolAddress((void**)&kl, g_kl);
    cudaGetSymbolAddress((void**)&vf, g_vf);
    cudaGetSymbolAddress((void**)&cf, g_cf);

    zero_kernel<<<1024, 256>>>();   // bitmap + flag count

    for (int i = 0; i < 4; i++)
        split_kernel<<<(D_ * D_) / 256, 256>>>(W[i], wh + (size_t)i * D_ * D_,
                                               wl + (size_t)i * D_ * D_, D_ * D_);

    cudaFuncSetAttribute(gemm_qkv, cudaFuncAttributeMaxDynamicSharedMemorySize,
                         51200);
    dim3 gp(D_ / 64, M_ / 128);   // (8, 64)
    gemm_qkv<<<gp, 256, 51200>>>(x, wh, wl, qh, ql, kh, kl, vf);

    cudaFuncSetAttribute(fused_attn, cudaFuncAttributeMaxDynamicSharedMemorySize,
                         SMEMTOT);
    dim3 ga(64, B_);              // 128 CTAs, interleaved balanced tiles
    fused_attn<<<ga, 512, SMEMTOT>>>(qh, kh, vf);

    fixup_kernel<<<1024, 32>>>(qh, ql, kh, kl, vf);

    gemm_out<<<gp, 256>>>(cf, wh + (size_t)3 * D_ * D_, wl + (size_t)3 * D_ * D_, out);
}

// round 15
// speedup vs baseline: 1.0842x; 1.0842x over previous
#include <cuda_runtime.h>
#include <cuda_fp16.h>

typedef __half fp16;

#define B_ 2
#define S_ 4096
#define D_ 512
#define M_ (B_ * S_)
#define MAXFLAG (1 << 18)

// ---------------- scratch ----------------
__device__ fp16 g_wh[4][D_ * D_];
__device__ fp16 g_wl[4][D_ * D_];
__device__ fp16 g_qh[(size_t)M_ * D_];
__device__ fp16 g_ql[(size_t)M_ * D_];
__device__ fp16 g_kh[(size_t)M_ * D_];
__device__ fp16 g_kl[(size_t)M_ * D_];
__device__ fp16 g_vf[(size_t)M_ * D_];
__device__ float g_cf[(size_t)M_ * D_];           // ctx fp32 (pre-fixup)
__device__ int g_nflag;
__device__ unsigned g_flags[MAXFLAG];

// ---------------- ptx helpers ----------------
__device__ __forceinline__ unsigned smaddr(const void* p) {
    return (unsigned)__cvta_generic_to_shared(p);
}
__device__ __forceinline__ void ldsm4(unsigned* r, unsigned a) {
    asm volatile("ldmatrix.sync.aligned.m8n8.x4.shared.b16 {%0,%1,%2,%3},[%4];"
                 : "=r"(r[0]), "=r"(r[1]), "=r"(r[2]), "=r"(r[3]) : "r"(a));
}
__device__ __forceinline__ void ldsm2(unsigned* r, unsigned a) {
    asm volatile("ldmatrix.sync.aligned.m8n8.x2.shared.b16 {%0,%1},[%2];"
                 : "=r"(r[0]), "=r"(r[1]) : "r"(a));
}
__device__ __forceinline__ void ldsm2t(unsigned* r, unsigned a) {
    asm volatile("ldmatrix.sync.aligned.m8n8.x2.trans.shared.b16 {%0,%1},[%2];"
                 : "=r"(r[0]), "=r"(r[1]) : "r"(a));
}
__device__ __forceinline__ void mma16816h(float* c, const unsigned* a, const unsigned* b) {
    asm volatile(
        "mma.sync.aligned.m16n8k16.row.col.f32.f16.f16.f32 "
        "{%0,%1,%2,%3},{%4,%5,%6,%7},{%8,%9},{%0,%1,%2,%3};"
        : "+f"(c[0]), "+f"(c[1]), "+f"(c[2]), "+f"(c[3])
        : "r"(a[0]), "r"(a[1]), "r"(a[2]), "r"(a[3]), "r"(b[0]), "r"(b[1]));
}
__device__ __forceinline__ void cpa16(unsigned d, const void* g) {
    asm volatile("cp.async.cg.shared.global [%0], [%1], 16;" :: "r"(d), "l"(g));
}
__device__ __forceinline__ void cpcommit() { asm volatile("cp.async.commit_group;"); }
__device__ __forceinline__ void cpwait0()  { asm volatile("cp.async.wait_group 0;" ::: "memory"); }

// ---------------- small utility kernels ----------------
__global__ void zero_flag_kernel() { g_nflag = 0; }

// split all 4 weights in one launch: grid (D*D/256, 4)
__global__ __launch_bounds__(256) void split4_kernel(
    const float* __restrict__ w0, const float* __restrict__ w1,
    const float* __restrict__ w2, const float* __restrict__ w3,
    fp16* __restrict__ hi, fp16* __restrict__ lo)
{
    int wsel = blockIdx.y;
    const float* in = (wsel == 0) ? w0 : (wsel == 1) ? w1 : (wsel == 2) ? w2 : w3;
    int i = blockIdx.x * 256 + threadIdx.x;
    float v = in[i];
    fp16 h = __float2half_rn(v);
    size_t off = (size_t)wsel * D_ * D_ + i;
    hi[off] = h;
    lo[off] = __float2half_rn(v - __half2float(h));
}

// ---------------- merged QKV projection (2-term: Ah*(Bh+Bl)) ----------------
__global__ __launch_bounds__(256) void gemm_qkv(
    const float* __restrict__ x,
    const fp16* __restrict__ wh, const fp16* __restrict__ wl,
    fp16* __restrict__ qh, fp16* __restrict__ ql,
    fp16* __restrict__ kh, fp16* __restrict__ kl,
    fp16* __restrict__ vf)
{
    extern __shared__ fp16 qkvsm[];
    fp16* sAh = qkvsm;                 // 128*40
    // weights at qkvsm + 5120 + (w*2+half)*2560

    const int tid = threadIdx.x, lane = tid & 31, warp = tid >> 5;
    const int m0 = blockIdx.y * 128, n0 = blockIdx.x * 64;
    const int wm = warp >> 1, wn = warp & 1;

    float acc[3][2][4][4];
#pragma unroll
    for (int w = 0; w < 3; w++)
#pragma unroll
        for (int a = 0; a < 2; a++)
#pragma unroll
            for (int b = 0; b < 4; b++)
#pragma unroll
                for (int c = 0; c < 4; c++) acc[w][a][b][c] = 0.0f;

    for (int k0 = 0; k0 < 512; k0 += 32) {
        __syncthreads();
        // stage A-hi only: 128 rows x 32 fp32 -> fp16 hi
#pragma unroll
        for (int j = 0; j < 4; j++) {
            int u = tid + j * 256;
            int row = u >> 3, c4 = u & 7;
            float4 v = *(const float4*)&x[(size_t)(m0 + row) * 512 + k0 + c4 * 4];
            int off = row * 40 + c4 * 4;
            *(__half2*)&sAh[off]     = __floats2half2_rn(v.x, v.y);
            *(__half2*)&sAh[off + 2] = __floats2half2_rn(v.z, v.w);
        }
        // stage W: 3 weights x hi/lo x 64 rows x 4 chunks = 1536
#pragma unroll
        for (int j = 0; j < 6; j++) {
            int u = tid + j * 256;
            int w = u >> 9, rem = u & 511;
            int hh = rem >> 8, r2 = rem & 255;
            int row = r2 >> 2, c4 = r2 & 3;
            const fp16* src = (hh ? wl : wh) + (size_t)w * D_ * D_
                              + (size_t)(n0 + row) * 512 + k0 + c4 * 8;
            fp16* dst = qkvsm + 5120 + (w * 2 + hh) * 2560 + row * 40 + c4 * 8;
            *(uint4*)dst = *(const uint4*)src;
        }
        __syncthreads();

#pragma unroll
        for (int kc = 0; kc < 2; kc++) {
            unsigned ah[2][4];
#pragma unroll
            for (int mi = 0; mi < 2; mi++) {
                int r = wm * 32 + mi * 16 + (lane & 15);
                int cc = kc * 16 + (lane >> 4) * 8;
                ldsm4(ah[mi], smaddr(&sAh[r * 40 + cc]));
            }
#pragma unroll
            for (int w = 0; w < 3; w++) {
#pragma unroll
                for (int ni = 0; ni < 4; ni++) {
                    int r = wn * 32 + ni * 8 + (lane & 7);
                    int cc = kc * 16 + ((lane >> 3) & 1) * 8;
                    const fp16* wbh = qkvsm + 5120 + (w * 2 + 0) * 2560;
                    const fp16* wbl = qkvsm + 5120 + (w * 2 + 1) * 2560;
                    unsigned bh[2], bl[2];
                    ldsm2(bh, smaddr(&wbh[r * 40 + cc]));
                    ldsm2(bl, smaddr(&wbl[r * 40 + cc]));
#pragma unroll
                    for (int mi = 0; mi < 2; mi++) {
                        mma16816h(acc[w][mi][ni], ah[mi], bh);
                        mma16816h(acc[w][mi][ni], ah[mi], bl);
                    }
                }
            }
        }
    }

#pragma unroll
    for (int w = 0; w < 3; w++)
#pragma unroll
        for (int mi = 0; mi < 2; mi++)
#pragma unroll
            for (int ni = 0; ni < 4; ni++)
#pragma unroll
                for (int half = 0; half < 2; half++) {
                    int row = m0 + wm * 32 + mi * 16 + (lane >> 2) + half * 8;
                    int col = n0 + wn * 32 + ni * 8 + (lane & 3) * 2;
                    float v0 = acc[w][mi][ni][half * 2 + 0];
                    float v1 = acc[w][mi][ni][half * 2 + 1];
                    size_t off = (size_t)row * 512 + col;
                    if (w == 2) {
                        *(__half2*)&vf[off] = __floats2half2_rn(v0, v1);
                    } else {
                        fp16 h0 = __float2half_rn(v0), h1 = __float2half_rn(v1);
                        fp16 l0 = __float2half_rn(v0 - __half2float(h0));
                        fp16 l1 = __float2half_rn(v1 - __half2float(h1));
                        fp16* Ch = (w == 0) ? qh : kh;
                        fp16* Cl = (w == 0) ? ql : kl;
                        *(__half2*)&Ch[off] = __half2(h0, h1);
                        *(__half2*)&Cl[off] = __half2(l0, l1);
                    }
                }
}

// ---------------- output projection (2-term: Ah*(Bh+Bl)), relu fp32 out -----
__global__ __launch_bounds__(256) void gemm_out(
    const float* __restrict__ A,
    const fp16* __restrict__ Wh, const fp16* __restrict__ Wl,
    float* __restrict__ Cf)
{
    __shared__ fp16 sAh[128 * 40], sWh[64 * 40], sWl[64 * 40];

    const int tid = threadIdx.x, lane = tid & 31, warp = tid >> 5;
    const int m0 = blockIdx.y * 128, n0 = blockIdx.x * 64;
    const int wm = warp >> 1, wn = warp & 1;

    float acc[2][4][4];
#pragma unroll
    for (int a = 0; a < 2; a++)
#pragma unroll
        for (int b = 0; b < 4; b++)
#pragma unroll
            for (int c = 0; c < 4; c++) acc[a][b][c] = 0.0f;

    for (int k0 = 0; k0 < 512; k0 += 32) {
        __syncthreads();
#pragma unroll
        for (int j = 0; j < 4; j++) {
            int u = tid + j * 256;
            int row = u >> 3, c4 = u & 7;
            float4 v = *(const float4*)&A[(size_t)(m0 + row) * 512 + k0 + c4 * 4];
            int off = row * 40 + c4 * 4;
            *(__half2*)&sAh[off]     = __floats2half2_rn(v.x, v.y);
            *(__half2*)&sAh[off + 2] = __floats2half2_rn(v.z, v.w);
        }
#pragma unroll
        for (int j = 0; j < 2; j++) {
            int u = tid + j * 256;
            int half = u >> 8, rem = u & 255;
            int row = rem >> 2, c4 = rem & 3;
            const fp16* src = (half ? Wl : Wh) + (size_t)(n0 + row) * 512 + k0 + c4 * 8;
            fp16* dst = (half ? sWl : sWh) + row * 40 + c4 * 8;
            *(uint4*)dst = *(const uint4*)src;
        }
        __syncthreads();

#pragma unroll
        for (int kc = 0; kc < 2; kc++) {
            unsigned ah[2][4];
#pragma unroll
            for (int mi = 0; mi < 2; mi++) {
                int r = wm * 32 + mi * 16 + (lane & 15);
                int cc = kc * 16 + (lane >> 4) * 8;
                ldsm4(ah[mi], smaddr(&sAh[r * 40 + cc]));
            }
#pragma unroll
            for (int ni = 0; ni < 4; ni++) {
                int r = wn * 32 + ni * 8 + (lane & 7);
                int cc = kc * 16 + ((lane >> 3) & 1) * 8;
                unsigned bh[2], bl[2];
                ldsm2(bh, smaddr(&sWh[r * 40 + cc]));
                ldsm2(bl, smaddr(&sWl[r * 40 + cc]));
#pragma unroll
                for (int mi = 0; mi < 2; mi++) {
                    mma16816h(acc[mi][ni], ah[mi], bh);
                    mma16816h(acc[mi][ni], ah[mi], bl);
                }
            }
        }
    }

#pragma unroll
    for (int mi = 0; mi < 2; mi++)
#pragma unroll
        for (int ni = 0; ni < 4; ni++)
#pragma unroll
            for (int half = 0; half < 2; half++) {
                int row = m0 + wm * 32 + mi * 16 + (lane >> 2) + half * 8;
                int col = n0 + wn * 32 + ni * 8 + (lane & 3) * 2;
                float v0 = acc[mi][ni][half * 2 + 0];
                float v1 = acc[mi][ni][half * 2 + 1];
                *(float2*)&Cf[(size_t)row * 512 + col] =
                    make_float2(fmaxf(v0, 0.f), fmaxf(v1, 0.f));
            }
}

// ---------------- fused attention (verbatim round 12: best measured) --------
#define QSTR 520
#define KVELEM 33280
#define SSCOFF 133120
#define SCH 2304
#define SATOFF 206848
#define ATH 1536
#define SMEMTOT 231424

__global__ __launch_bounds__(512, 1) void fused_attn(
    const fp16* __restrict__ qhp, const fp16* __restrict__ khp,
    const fp16* __restrict__ vfp)
{
    extern __shared__ char smem[];
    fp16* kv = (fp16*)smem;
    float* ssc = (float*)(smem + SSCOFF);
    fp16* sat = (fp16*)(smem + SATOFF);

    const int tid = threadIdx.x, lane = tid & 31, w = tid >> 5;
    const int h = w & 7, qhalf = w >> 3;
    const int qt = blockIdx.x, b = blockIdx.y;
    const size_t kvbase = (size_t)b * S_ * D_;
    const int qg0 = qt * 64;
    const int browbase = b * S_;

#pragma unroll
    for (int j = 0; j < 8; j++) {
        int u = tid + j * 512;
        int row = u >> 6, cc = u & 63;
        const fp16* src = qhp + (size_t)(browbase + qg0 + row) * 512 + cc * 8;
        *(uint4*)&kv[row * QSTR + cc * 8] = *(const uint4*)src;
    }
    __syncthreads();

    unsigned qf[2][4][4];
#pragma unroll
    for (int mi = 0; mi < 2; mi++)
#pragma unroll
        for (int dc = 0; dc < 4; dc++) {
            int row = qhalf * 32 + mi * 16 + (lane & 15);
            int col = h * 64 + dc * 16 + (lane >> 4) * 8;
            ldsm4(qf[mi][dc], smaddr(&kv[row * QSTR + col]));
        }
    __syncthreads();

    float cacc[2][8][4];
#pragma unroll
    for (int mi = 0; mi < 2; mi++)
#pragma unroll
        for (int ni = 0; ni < 8; ni++)
#pragma unroll
            for (int c = 0; c < 4; c++) cacc[mi][ni][c] = 0.0f;

#pragma unroll
    for (int j = 0; j < 8; j++) {
        int c = tid + j * 512;
        int arr = c >> 11, rem = c & 2047;
        int r = rem >> 6, cc = rem & 63;
        size_t goff = kvbase + (size_t)r * 512 + cc * 8;
        const fp16* src = (arr == 0) ? (khp + goff) : (vfp + goff);
        cpa16(smaddr(kv + arr * 16640 + r * 520 + cc * 8), src);
    }
    cpcommit();

    for (int it = 0; it < 128; it++) {
        fp16* buf = kv + (it & 1) * KVELEM;
        const fp16* Kf = buf;
        const fp16* Vf = buf + 16640;
        const int kbase = it * 32;

        cpwait0();
        __syncthreads();

        if (it + 1 < 128) {
            fp16* nb = kv + ((it + 1) & 1) * KVELEM;
            const size_t rowoff = kvbase + (size_t)(it + 1) * 32 * 512;
#pragma unroll
            for (int j = 0; j < 8; j++) {
                int c = tid + j * 512;
                int arr = c >> 11, rem = c & 2047;
                int r = rem >> 6, cc = rem & 63;
                size_t goff = rowoff + (size_t)r * 512 + cc * 8;
                const fp16* src = (arr == 0) ? (khp + goff) : (vfp + goff);
                cpa16(smaddr(nb + arr * 16640 + r * 520 + cc * 8), src);
            }
            cpcommit();
        }

#pragma unroll
        for (int kc = 0; kc < 2; kc++) {
            float cs[2][2][4];
#pragma unroll
            for (int mi = 0; mi < 2; mi++)
#pragma unroll
                for (int ni = 0; ni < 2; ni++)
#pragma unroll
                    for (int c = 0; c < 4; c++) cs[mi][ni][c] = 0.0f;

#pragma unroll
            for (int dc = 0; dc < 4; dc++) {
                unsigned k2[2][2];
#pragma unroll
                for (int ni = 0; ni < 2; ni++) {
                    int kr = kc * 16 + ni * 8 + (lane & 7);
                    int col = h * 64 + dc * 16 + ((lane >> 3) & 1) * 8;
                    ldsm2(k2[ni], smaddr(&Kf[kr * 520 + col]));
                }
#pragma unroll
                for (int mi = 0; mi < 2; mi++)
#pragma unroll
                    for (int ni = 0; ni < 2; ni++)
                        mma16816h(cs[mi][ni], qf[mi][dc], k2[ni]);
            }
#pragma unroll
            for (int mi = 0; mi < 2; mi++)
#pragma unroll
                for (int ni = 0; ni < 2; ni++) {
                    int row = qhalf * 32 + mi * 16 + (lane >> 2);
                    int col = kc * 16 + ni * 8 + (lane & 3) * 2;
                    *(float2*)&ssc[h * SCH + row * 36 + col] =
                        make_float2(cs[mi][ni][0], cs[mi][ni][1]);
                    *(float2*)&ssc[h * SCH + (row + 8) * 36 + col] =
                        make_float2(cs[mi][ni][2], cs[mi][ni][3]);
                }
        }
        __syncthreads();

#pragma unroll
        for (int sub = 0; sub < 2; sub++) {
            {
                int q = tid >> 3;
                int kl = (tid & 7) * 2;
                int qg = qg0 + q;
                int kg = kbase + sub * 16 + kl;

                float2 s2[8];
#pragma unroll
                for (int hh = 0; hh < 8; hh++)
                    s2[hh] = *(float2*)&ssc[hh * SCH + q * 36 + sub * 16 + kl];

                float p0[8], p1[8];
                if (kg > qg) {
                    float mx = fabsf(s2[0].x);
#pragma unroll
                    for (int hh = 1; hh < 8; hh++) mx = fmaxf(mx, fabsf(s2[hh].x));
                    if (mx >= 31.5f) {
                        int idx = atomicAdd(&g_nflag, 1);
                        if (idx < MAXFLAG)
                            g_flags[idx] = ((unsigned)b << 24) | ((unsigned)qg << 12) | (unsigned)kg;
                    }
#pragma unroll
                    for (int hh = 0; hh < 8; hh++) p0[hh] = 0.125f;
                } else {
                    float sum = 0.0f;
#pragma unroll
                    for (int hh = 0; hh < 8; hh++) {
                        p0[hh] = __expf(s2[hh].x * 0.125f);
                        sum += p0[hh];
                    }
                    float inv = 1.0f / sum;
#pragma unroll
                    for (int hh = 0; hh < 8; hh++) p0[hh] *= inv;
                }
                if (kg + 1 > qg) {
                    float mx = fabsf(s2[0].y);
#pragma unroll
                    for (int hh = 1; hh < 8; hh++) mx = fmaxf(mx, fabsf(s2[hh].y));
                    if (mx >= 31.5f) {
                        int idx = atomicAdd(&g_nflag, 1);
                        if (idx < MAXFLAG)
                            g_flags[idx] = ((unsigned)b << 24) | ((unsigned)qg << 12) | (unsigned)(kg + 1);
                    }
#pragma unroll
                    for (int hh = 0; hh < 8; hh++) p1[hh] = 0.125f;
                } else {
                    float sum = 0.0f;
#pragma unroll
                    for (int hh = 0; hh < 8; hh++) {
                        p1[hh] = __expf(s2[hh].y * 0.125f);
                        sum += p1[hh];
                    }
                    float inv = 1.0f / sum;
#pragma unroll
                    for (int hh = 0; hh < 8; hh++) p1[hh] *= inv;
                }
#pragma unroll
                for (int hh = 0; hh < 8; hh++)
                    *(__half2*)&sat[hh * ATH + q * 24 + kl] =
                        __floats2half2_rn(p0[hh], p1[hh]);
            }
            __syncthreads();

            {
                unsigned af[2][4];
#pragma unroll
                for (int mi = 0; mi < 2; mi++) {
                    int row = qhalf * 32 + mi * 16 + (lane & 15);
                    ldsm4(af[mi], smaddr(&sat[h * ATH + row * 24 + (lane >> 4) * 8]));
                }
#pragma unroll
                for (int ni = 0; ni < 8; ni++) {
                    unsigned v2[2];
                    ldsm2t(v2, smaddr(&Vf[(sub * 16 + (lane & 15)) * 520 + h * 64 + ni * 8]));
#pragma unroll
                    for (int mi = 0; mi < 2; mi++)
                        mma16816h(cacc[mi][ni], af[mi], v2);
                }
            }
            if (sub == 0) __syncthreads();
        }
    }

#pragma unroll
    for (int mi = 0; mi < 2; mi++)
#pragma unroll
        for (int ni = 0; ni < 8; ni++)
#pragma unroll
            for (int hf = 0; hf < 2; hf++) {
                int row = browbase + qg0 + qhalf * 32 + mi * 16 + (lane >> 2) + hf * 8;
                int col = h * 64 + ni * 8 + (lane & 3) * 2;
                size_t off = (size_t)row * 512 + col;
                *(float2*)&g_cf[off] =
                    make_float2(cacc[mi][ni][hf * 2 + 0], cacc[mi][ni][hf * 2 + 1]);
            }
}

// ---------------- fixup (verbatim round 12) ---------------------------------
__global__ __launch_bounds__(32) void fixup_kernel(
    const fp16* __restrict__ qh, const fp16* __restrict__ ql,
    const fp16* __restrict__ kh, const fp16* __restrict__ kl,
    const fp16* __restrict__ vf)
{
    const int lane = threadIdx.x;
    int count = g_nflag;
    if (count > MAXFLAG) count = MAXFLAG;

    for (int i = blockIdx.x; i < count; i += gridDim.x) {
        unsigned f = g_flags[i];
        int b = f >> 24;
        int qg = (f >> 12) & 4095;
        int kg = f & 4095;
        size_t qrow = (size_t)(b * S_ + qg) * 512;
        size_t krow = (size_t)(b * S_ + kg) * 512;

        float t[8];
#pragma unroll
        for (int hh = 0; hh < 8; hh++) {
            float se = 0.0f;
#pragma unroll
            for (int r = 0; r < 2; r++) {
                int d = hh * 64 + r * 32 + lane;
                float qv = __half2float(qh[qrow + d]) + __half2float(ql[qrow + d]);
                float kv = __half2float(kh[krow + d]) + __half2float(kl[krow + d]);
                se = fmaf(qv, kv, se);
            }
#pragma unroll
            for (int o = 16; o; o >>= 1)
                se += __shfl_xor_sync(0xFFFFFFFFu, se, o);
            t[hh] = 8.0f * rintf(se * 0.015625f);
        }
        float e[8], sum = 0.0f;
#pragma unroll
        for (int hh = 0; hh < 8; hh++) { e[hh] = __expf(t[hh]); sum += e[hh]; }
        float inv = 1.0f / sum;

#pragma unroll
        for (int j = 0; j < 16; j++) {
            int c = j * 32 + lane;
            int hh = c >> 6;
            float corr = (e[hh] * inv - 0.125f) * __half2float(vf[krow + c]);
            atomicAdd(&g_cf[qrow + c], corr);
        }
    }
}

// ---------------------------------------------------------------------------
extern "C" void kernel_launch(void* const* d_in, const int* in_sizes, int n_in,
                              void* d_out, int out_size)
{
    const float* x  = (const float*)d_in[0];
    const float* W[4] = {(const float*)d_in[1], (const float*)d_in[2],
                         (const float*)d_in[3], (const float*)d_in[4]};
    float* out = (float*)d_out;

    fp16 *wh, *wl, *qh, *ql, *kh, *kl, *vf;
    float* cf;
    cudaGetSymbolAddress((void**)&wh, g_wh);
    cudaGetSymbolAddress((void**)&wl, g_wl);
    cudaGetSymbolAddress((void**)&qh, g_qh);
    cudaGetSymbolAddress((void**)&ql, g_ql);
    cudaGetSymbolAddress((void**)&kh, g_kh);
    cudaGetSymbolAddress((void**)&kl, g_kl);
    cudaGetSymbolAddress((void**)&vf, g_vf);
    cudaGetSymbolAddress((void**)&cf, g_cf);

    zero_flag_kernel<<<1, 1>>>();

    dim3 gs(D_ * D_ / 256, 4);
    split4_kernel<<<gs, 256>>>(W[0], W[1], W[2], W[3], wh, wl);

    cudaFuncSetAttribute(gemm_qkv, cudaFuncAttributeMaxDynamicSharedMemorySize,
                         40960);
    dim3 gp(D_ / 64, M_ / 128);   // (8, 64)
    gemm_qkv<<<gp, 256, 40960>>>(x, wh, wl, qh, ql, kh, kl, vf);

    cudaFuncSetAttribute(fused_attn, cudaFuncAttributeMaxDynamicSharedMemorySize,
                         SMEMTOT);
    dim3 ga(S_ / 64, B_);         // (64, 2) = 128 CTAs, one full wave
    fused_attn<<<ga, 512, SMEMTOT>>>(qh, kh, vf);

    fixup_kernel<<<1024, 32>>>(qh, ql, kh, kl, vf);

    gemm_out<<<gp, 256>>>(cf, wh + (size_t)3 * D_ * D_, wl + (size_t)3 * D_ * D_, out);
}